// round 6
// baseline (speedup 1.0000x reference)
#include <cuda_runtime.h>
#include <math.h>

#define BATCH 256
#define NA 8192
#define NE 262144
#define NACT 21
#define LOG2E 1.4426950408889634f
#define LN2   0.6931471805599453f

// ---------------- scratch (device globals; no allocs allowed) ----------------
__device__ float g_c1[BATCH * 1152];   // [256,32,6,6]
__device__ float g_c2[BATCH * 1024];   // [256,64,4,4] flattened
__device__ float g_hidden[BATCH * 512];
__device__ float g_ae0[NA];
__device__ float g_dinv[NA];
__device__ int   g_deg[NA];
__device__ float g_agg[NA * 16];
__device__ float g_agg2[NA * 16];
__device__ float g_w2t[NA * 16];   // gcn2_w^T, pre-scaled by LOG2E
__device__ float g_b2l[NA];        // gcn2_b * LOG2E
__device__ float g_colsum[16];     // LOG2E * column sums of gcn2_w (over j)
__device__ float g_sumb2l;         // LOG2E * sum of gcn2_b

__device__ __forceinline__ float fexp2(float x) {
    float y; asm("ex2.approx.ftz.f32 %0, %1;" : "=f"(y) : "f"(x)); return y;
}
__device__ __forceinline__ float flog2(float x) {
    float y; asm("lg2.approx.ftz.f32 %0, %1;" : "=f"(y) : "f"(x)); return y;
}
__device__ __forceinline__ void red4(float* p, float a, float b, float c, float d) {
    asm volatile("red.global.add.v4.f32 [%0], {%1,%2,%3,%4};"
                 :: "l"(p), "f"(a), "f"(b), "f"(c), "f"(d) : "memory");
}
__device__ __forceinline__ unsigned long long ffma2(unsigned long long a,
                                                    unsigned long long b,
                                                    unsigned long long c) {
    unsigned long long d;
    asm("fma.rn.f32x2 %0, %1, %2, %3;" : "=l"(d) : "l"(a), "l"(b), "l"(c));
    return d;
}
__device__ __forceinline__ unsigned long long packf2(float lo, float hi) {
    unsigned long long r;
    asm("mov.b64 %0, {%1,%2};" : "=l"(r) : "f"(lo), "f"(hi));
    return r;
}
__device__ __forceinline__ void unpackf2(unsigned long long v, float& lo, float& hi) {
    asm("mov.b64 {%0,%1}, %2;" : "=f"(lo), "=f"(hi) : "l"(v));
}

// ---------------- conv1: smem-staged, one block per batch image ------------
__global__ void __launch_bounds__(256) conv1_kernel(const float* __restrict__ x,
                                                    const float* __restrict__ w,
                                                    const float* __restrict__ b) {
    __shared__ float xs[845];    // 5*13*13
    __shared__ float ws[1440];   // 32*45
    __shared__ float bs[32];
    int bb = blockIdx.x, t = threadIdx.x;
    for (int i = t; i < 845; i += 256) xs[i] = x[bb * 845 + i];
    for (int i = t; i < 1440; i += 256) ws[i] = w[i];
    if (t < 32) bs[t] = b[t];
    __syncthreads();
    for (int o = t; o < 1152; o += 256) {
        int oc = o / 36, r = o % 36, oy = r / 6, ox = r % 6;
        const float* wp = ws + oc * 45;
        const float* xp = xs + 2 * oy * 13 + 2 * ox;
        float acc = bs[oc];
#pragma unroll
        for (int ic = 0; ic < 5; ic++)
#pragma unroll
            for (int ky = 0; ky < 3; ky++)
#pragma unroll
                for (int kx = 0; kx < 3; kx++)
                    acc += xp[ic * 169 + ky * 13 + kx] * wp[ic * 9 + ky * 3 + kx];
        g_c1[bb * 1152 + o] = fmaxf(acc, 0.f);
    }
}

// ---------------- conv2 as implicit GEMM: [32 rows x 64 oc] x K=288 --------
// rows = 2 batches x 16 positions; on-the-fly im2col from smem-staged images
__global__ void __launch_bounds__(256) conv2_kernel(const float* __restrict__ w,
                                                    const float* __restrict__ b) {
    __shared__ float imgs[2 * 1152];
    __shared__ __align__(16) float2 As2[16][33];  // [kk][row] duplicated (a,a)
    __shared__ __align__(16) float Bs[16][66];    // [kk][oc]
    int bb0 = blockIdx.x * 2;
    int tid = threadIdx.x;
    for (int i = tid; i < 2304; i += 256) imgs[i] = g_c1[bb0 * 1152 + i];

    int tx = tid & 15, ty = tid >> 4;
    // A-loader coords (2 kk per thread, 32 rows)
    int l_row = tid & 31;
    int l_kk0 = (tid >> 5) * 2;
    int l_pos = l_row & 15;
    int l_base = (l_row >> 4) * 1152 + (l_pos >> 2) * 6 + (l_pos & 3);
    // B-loader coords (4 kk per thread, 64 oc)
    int b_oc = tid & 63;
    int b_kk0 = (tid >> 6) * 4;

    unsigned long long acc00 = 0, acc01 = 0, acc10 = 0, acc11 = 0;

    for (int k0 = 0; k0 < 288; k0 += 16) {
        __syncthreads();
        float4 wv = *(const float4*)(w + b_oc * 288 + k0 + b_kk0);
        Bs[b_kk0][b_oc]     = wv.x;
        Bs[b_kk0 + 1][b_oc] = wv.y;
        Bs[b_kk0 + 2][b_oc] = wv.z;
        Bs[b_kk0 + 3][b_oc] = wv.w;
#pragma unroll
        for (int u = 0; u < 2; u++) {
            int k = k0 + l_kk0 + u;
            int ic = (k * 57) >> 9;        // k/9 for k<460
            int r9 = k - ic * 9;
            int ky = (r9 * 11) >> 5;       // r9/3
            int kx = r9 - ky * 3;
            float v = imgs[l_base + ic * 36 + ky * 6 + kx];
            As2[l_kk0 + u][l_row] = make_float2(v, v);
        }
        __syncthreads();
#pragma unroll
        for (int kk = 0; kk < 16; kk++) {
            unsigned long long a0 = *(const unsigned long long*)&As2[kk][ty * 2];
            unsigned long long a1 = *(const unsigned long long*)&As2[kk][ty * 2 + 1];
            unsigned long long bp0 = *(const unsigned long long*)&Bs[kk][tx * 4];
            unsigned long long bp1 = *(const unsigned long long*)&Bs[kk][tx * 4 + 2];
            acc00 = ffma2(a0, bp0, acc00);
            acc01 = ffma2(a0, bp1, acc01);
            acc10 = ffma2(a1, bp0, acc10);
            acc11 = ffma2(a1, bp1, acc11);
        }
    }

    int c = tx * 4;
    float4 bv = *(const float4*)(b + c);
    float v00, v01, v02, v03, v10, v11, v12, v13;
    unpackf2(acc00, v00, v01);
    unpackf2(acc01, v02, v03);
    unpackf2(acc10, v10, v11);
    unpackf2(acc11, v12, v13);
    int r0 = ty * 2;
    int bi = r0 >> 4;
    int pos0 = r0 & 15, pos1 = pos0 + 1;
    float* o0 = g_c2 + (bb0 + bi) * 1024 + pos0;
    float* o1 = g_c2 + (bb0 + bi) * 1024 + pos1;
    o0[(c + 0) * 16] = fmaxf(v00 + bv.x, 0.f);
    o0[(c + 1) * 16] = fmaxf(v01 + bv.y, 0.f);
    o0[(c + 2) * 16] = fmaxf(v02 + bv.z, 0.f);
    o0[(c + 3) * 16] = fmaxf(v03 + bv.w, 0.f);
    o1[(c + 0) * 16] = fmaxf(v10 + bv.x, 0.f);
    o1[(c + 1) * 16] = fmaxf(v11 + bv.y, 0.f);
    o1[(c + 2) * 16] = fmaxf(v12 + bv.z, 0.f);
    o1[(c + 3) * 16] = fmaxf(v13 + bv.w, 0.f);
}

// ---------------- FC: 32x32 tiles, 2x2 microtile, f32x2 FFMA2 --------------
__global__ void __launch_bounds__(256) fc_kernel(const float* __restrict__ W,  // [512,1024]
                                                 const float* __restrict__ b) {
    __shared__ float2 As2[16][33];
    __shared__ float  Bs[16][34];
    int tid = threadIdx.x;
    int tx = tid & 15, ty = tid >> 4;
    int row0 = blockIdx.y * 32, col0 = blockIdx.x * 32;
    int lrow = tid >> 3;
    int lkk  = (tid & 7) * 2;
    unsigned long long acc0 = 0ULL, acc1 = 0ULL;
    for (int k0 = 0; k0 < 1024; k0 += 16) {
        float2 av = *(const float2*)(g_c2 + (row0 + lrow) * 1024 + k0 + lkk);
        float2 bv = *(const float2*)(W + (col0 + lrow) * 1024 + k0 + lkk);
        As2[lkk][lrow]     = make_float2(av.x, av.x);
        As2[lkk + 1][lrow] = make_float2(av.y, av.y);
        Bs[lkk][lrow]      = bv.x;
        Bs[lkk + 1][lrow]  = bv.y;
        __syncthreads();
#pragma unroll
        for (int kk = 0; kk < 16; kk++) {
            unsigned long long a0 = *(const unsigned long long*)&As2[kk][ty * 2];
            unsigned long long a1 = *(const unsigned long long*)&As2[kk][ty * 2 + 1];
            unsigned long long bp = *(const unsigned long long*)&Bs[kk][tx * 2];
            acc0 = ffma2(a0, bp, acc0);
            acc1 = ffma2(a1, bp, acc1);
        }
        __syncthreads();
    }
    float o00, o01, o10, o11;
    unpackf2(acc0, o00, o01);
    unpackf2(acc1, o10, o11);
    int r0 = row0 + ty * 2, c0 = col0 + tx * 2;
    float b0 = b[c0], b1 = b[c0 + 1];
    g_hidden[r0 * 512 + c0]           = fmaxf(o00 + b0, 0.f);
    g_hidden[r0 * 512 + c0 + 1]       = fmaxf(o01 + b1, 0.f);
    g_hidden[(r0 + 1) * 512 + c0]     = fmaxf(o10 + b0, 0.f);
    g_hidden[(r0 + 1) * 512 + c0 + 1] = fmaxf(o11 + b1, 0.f);
}

// ---------------- logits + log_prob + entropy + action passthrough ----------
__global__ void logits_kernel(const float* __restrict__ Wmu,  // [21,512]
                              const float* __restrict__ bmu,
                              const int* __restrict__ action,
                              float* __restrict__ out_act,
                              float* __restrict__ lp_out,
                              float* __restrict__ ent_out) {
    __shared__ float lg[NACT];
    int bb = blockIdx.x;
    int lane = threadIdx.x;
    const float* h = g_hidden + bb * 512;
    for (int o = 0; o < NACT; o++) {
        const float* wr = Wmu + o * 512;
        float acc = 0.f;
        for (int k = lane; k < 512; k += 32) acc += h[k] * wr[k];
#pragma unroll
        for (int off = 16; off; off >>= 1) acc += __shfl_down_sync(0xffffffffu, acc, off);
        if (lane == 0) lg[o] = acc + bmu[o];
    }
    __syncwarp();
    if (lane == 0) {
        float m = -1e30f;
        for (int o = 0; o < NACT; o++) m = fmaxf(m, lg[o]);
        float s = 0.f;
        for (int o = 0; o < NACT; o++) s += expf(lg[o] - m);
        float lse = m + logf(s);
        float ent = 0.f;
        for (int o = 0; o < NACT; o++) {
            float lpo = lg[o] - lse;
            ent -= expf(lpo) * lpo;
        }
        lp_out[bb] = lg[action[bb]] - lse;
        ent_out[bb] = ent;
        out_act[bb] = (float)action[bb];
    }
}

// ---------------- actor_encoding row 0: GEMV (float4) -----------------------
__global__ void __launch_bounds__(256) ae0_kernel(const float* __restrict__ Wm,
                                                  const float* __restrict__ bm) {
    int wid = (blockIdx.x * blockDim.x + threadIdx.x) >> 5;
    int lane = threadIdx.x & 31;
    if (wid >= NA) return;
    const float4* wr = (const float4*)(Wm + wid * 512);
    const float4* hp = (const float4*)g_hidden;
    float acc = 0.f;
#pragma unroll
    for (int i = 0; i < 4; i++) {
        float4 w = wr[lane + 32 * i];
        float4 h = hp[lane + 32 * i];
        acc += w.x * h.x + w.y * h.y + w.z * h.z + w.w * h.w;
    }
#pragma unroll
    for (int off = 16; off; off >>= 1) acc += __shfl_down_sync(0xffffffffu, acc, off);
    if (lane == 0) g_ae0[wid] = acc + bm[wid];
}

// ---------------- graph prep ------------------------------------------------
__global__ void deg_kernel(const int* __restrict__ edge) {
    int idx = blockIdx.x * blockDim.x + threadIdx.x;
    if (idx >= NE) return;
    atomicAdd(&g_deg[edge[2 * idx + 1]], 1);
}

// dinv + b2l (idx<NA) and transpose gcn2_w with LOG2E pre-scale (idx<NA*16)
__global__ void dinv_w2t_kernel(const float* __restrict__ w2,   // [16, 8192]
                                const float* __restrict__ b2) {
    int idx = blockIdx.x * blockDim.x + threadIdx.x;
    if (idx < NA) {
        g_dinv[idx] = rsqrtf((float)(g_deg[idx] + 1));  // +1 self-loop
        g_b2l[idx] = b2[idx] * LOG2E;
    }
    if (idx >= NA * 16) return;
    int j = idx % NA, k = idx / NA;
    g_w2t[j * 16 + k] = w2[k * NA + j] * LOG2E;
}

// column sums of w2 (rows of [16,8192]) + sum of b2, scaled by LOG2E
__global__ void colsum_kernel(const float* __restrict__ w2,
                              const float* __restrict__ b2) {
    int warp = threadIdx.x >> 5, lane = threadIdx.x & 31;
    const float* src = (warp < 16) ? (w2 + warp * NA) : b2;
    const float4* p = (const float4*)src;
    float s = 0.f;
    for (int i = lane; i < NA / 4; i += 32) {
        float4 v = p[i];
        s += v.x + v.y + v.z + v.w;
    }
#pragma unroll
    for (int off = 16; off; off >>= 1) s += __shfl_down_sync(0xffffffffu, s, off);
    if (lane == 0) {
        if (warp < 16) g_colsum[warp] = s * LOG2E;
        else g_sumb2l = s * LOG2E;
    }
}

// ------- scatter1 (fused feats@gcn1_w): agg[dst] += norm * (feat(src)@W1) ---
__global__ void scatter1_kernel(const float* __restrict__ x_msg,
                                const int* __restrict__ edge,
                                const float* __restrict__ w1) {  // [2,16]
    __shared__ float w1s[32];
    if (threadIdx.x < 32) w1s[threadIdx.x] = w1[threadIdx.x];
    __syncthreads();
    int e = blockIdx.x * blockDim.x + threadIdx.x;
    if (e >= NE + NA) return;
    int src, dst; float norm;
    if (e < NE) {
        int2 ed = ((const int2*)edge)[e];
        src = ed.x; dst = ed.y;
        norm = g_dinv[src] * g_dinv[dst];
    } else {
        src = dst = e - NE;
        float d = g_dinv[src];
        norm = d * d;
    }
    float f0 = x_msg[src] * norm;
    float f1 = g_ae0[src] * norm;
    float* out = g_agg + dst * 16;
    float h[16];
#pragma unroll
    for (int k = 0; k < 16; k++) h[k] = f0 * w1s[k] + f1 * w1s[16 + k];
    red4(out +  0, h[0],  h[1],  h[2],  h[3]);
    red4(out +  4, h[4],  h[5],  h[6],  h[7]);
    red4(out +  8, h[8],  h[9],  h[10], h[11]);
    red4(out + 12, h[12], h[13], h[14], h[15]);
}

// ------- scatter2 (fused relu+bias): agg2[dst] += norm * relu(agg[src]+b1) --
__global__ void scatter2_kernel(const int* __restrict__ edge,
                                const float* __restrict__ b1) {  // [16]
    __shared__ float b1s[16];
    if (threadIdx.x < 16) b1s[threadIdx.x] = b1[threadIdx.x];
    __syncthreads();
    int e = blockIdx.x * blockDim.x + threadIdx.x;
    if (e >= NE + NA) return;
    int src, dst; float norm;
    if (e < NE) {
        int2 ed = ((const int2*)edge)[e];
        src = ed.x; dst = ed.y;
        norm = g_dinv[src] * g_dinv[dst];
    } else {
        src = dst = e - NE;
        float d = g_dinv[src];
        norm = d * d;
    }
    const float4* in = (const float4*)(g_agg + src * 16);
    float* out = g_agg2 + dst * 16;
    float h[16];
#pragma unroll
    for (int q = 0; q < 4; q++) {
        float4 v = in[q];
        h[4 * q + 0] = fmaxf(v.x + b1s[4 * q + 0], 0.f) * norm;
        h[4 * q + 1] = fmaxf(v.y + b1s[4 * q + 1], 0.f) * norm;
        h[4 * q + 2] = fmaxf(v.z + b1s[4 * q + 2], 0.f) * norm;
        h[4 * q + 3] = fmaxf(v.w + b1s[4 * q + 3], 0.f) * norm;
    }
    red4(out +  0, h[0],  h[1],  h[2],  h[3]);
    red4(out +  4, h[4],  h[5],  h[6],  h[7]);
    red4(out +  8, h[8],  h[9],  h[10], h[11]);
    red4(out + 12, h[12], h[13], h[14], h[15]);
}

// ---------------- fused g2-row GEMM + log_softmax mean ----------------------
// mean via precomputed column sums; se = sum exp2(vl) (no online max, bounded)
#define RPB 16
__global__ void __launch_bounds__(256)
rows_kernel(float* __restrict__ out) {
    __shared__ __align__(16) float aS[RPB][16];
    __shared__ float redse[8][RPB];
    int tid = threadIdx.x;
    int i0 = blockIdx.x * RPB;
    aS[tid >> 4][tid & 15] = g_agg2[i0 * 16 + tid];
    __syncthreads();

    float se[RPB];
#pragma unroll
    for (int r = 0; r < RPB; r++) se[r] = 0.f;

#pragma unroll 2
    for (int j = tid; j < NA; j += 256) {
        const ulonglong2* wp = (const ulonglong2*)(g_w2t + j * 16);
        ulonglong2 w0 = wp[0], w1 = wp[1], w2 = wp[2], w3 = wp[3];
        unsigned long long binit = packf2(g_b2l[j], 0.f);
#pragma unroll
        for (int r = 0; r < RPB; r++) {
            const ulonglong2* ap = (const ulonglong2*)aS[r];
            ulonglong2 a0 = ap[0], a1 = ap[1], a2 = ap[2], a3 = ap[3];
            unsigned long long acc = binit;
            acc = ffma2(a0.x, w0.x, acc);
            acc = ffma2(a0.y, w0.y, acc);
            acc = ffma2(a1.x, w1.x, acc);
            acc = ffma2(a1.y, w1.y, acc);
            acc = ffma2(a2.x, w2.x, acc);
            acc = ffma2(a2.y, w2.y, acc);
            acc = ffma2(a3.x, w3.x, acc);
            acc = ffma2(a3.y, w3.y, acc);
            float lo, hi;
            unpackf2(acc, lo, hi);
            se[r] += fexp2(lo + hi);
        }
    }

    int lane = tid & 31, warp = tid >> 5;
#pragma unroll
    for (int off = 16; off; off >>= 1) {
#pragma unroll
        for (int r = 0; r < RPB; r++)
            se[r] += __shfl_down_sync(0xffffffffu, se[r], off);
    }
    if (lane == 0) {
#pragma unroll
        for (int r = 0; r < RPB; r++) redse[warp][r] = se[r];
    }
    __syncthreads();
    if (tid < RPB) {
        int r = tid;
        float s = 0.f;
#pragma unroll
        for (int w = 0; w < 8; w++) s += redse[w][r];
        float mean = g_sumb2l;
#pragma unroll
        for (int k = 0; k < 16; k++) mean += aS[r][k] * g_colsum[k];
        out[i0 + r] = LN2 * (mean * (1.f / (float)NA) - flog2(s));
    }
}

// ---------------- launch -----------------------------------------------------
extern "C" void kernel_launch(void* const* d_in, const int* in_sizes, int n_in,
                              void* d_out, int out_size) {
    const float* x       = (const float*)d_in[0];
    const float* x_msg   = (const float*)d_in[1];
    const int*   edge    = (const int*)d_in[2];
    const int*   action  = (const int*)d_in[3];
    const float* conv1_w = (const float*)d_in[4];
    const float* conv1_b = (const float*)d_in[5];
    const float* conv2_w = (const float*)d_in[6];
    const float* conv2_b = (const float*)d_in[7];
    const float* fc_w    = (const float*)d_in[8];
    const float* fc_b    = (const float*)d_in[9];
    const float* fcmu_w  = (const float*)d_in[10];
    const float* fcmu_b  = (const float*)d_in[11];
    const float* msg_w   = (const float*)d_in[12];
    const float* msg_b   = (const float*)d_in[13];
    const float* gcn1_w  = (const float*)d_in[14];
    const float* gcn1_b  = (const float*)d_in[15];
    const float* gcn2_w  = (const float*)d_in[16];
    const float* gcn2_b  = (const float*)d_in[17];

    float* out = (float*)d_out;
    float* out_msg = out + BATCH;
    float* out_lp  = out + BATCH + NA;
    float* out_ent = out + BATCH + NA + BATCH;

    void *p_deg, *p_agg, *p_agg2;
    cudaGetSymbolAddress(&p_deg, g_deg);
    cudaGetSymbolAddress(&p_agg, g_agg);
    cudaGetSymbolAddress(&p_agg2, g_agg2);
    cudaMemsetAsync(p_deg, 0, NA * sizeof(int));
    cudaMemsetAsync(p_agg, 0, NA * 16 * sizeof(float));
    cudaMemsetAsync(p_agg2, 0, NA * 16 * sizeof(float));

    deg_kernel<<<(NE + 255) / 256, 256>>>(edge);
    dinv_w2t_kernel<<<(NA * 16 + 255) / 256, 256>>>(gcn2_w, gcn2_b);
    colsum_kernel<<<1, 17 * 32>>>(gcn2_w, gcn2_b);

    conv1_kernel<<<BATCH, 256>>>(x, conv1_w, conv1_b);
    conv2_kernel<<<BATCH / 2, 256>>>(conv2_w, conv2_b);
    fc_kernel<<<dim3(16, 8), 256>>>(fc_w, fc_b);
    logits_kernel<<<BATCH, 32>>>(fcmu_w, fcmu_b, action, out, out_lp, out_ent);
    ae0_kernel<<<NA * 32 / 256, 256>>>(msg_w, msg_b);

    scatter1_kernel<<<(NE + NA + 255) / 256, 256>>>(x_msg, edge, gcn1_w);
    scatter2_kernel<<<(NE + NA + 255) / 256, 256>>>(edge, gcn1_b);
    rows_kernel<<<NA / RPB, 256>>>(out_msg);
}

// round 7
// speedup vs baseline: 1.2223x; 1.2223x over previous
#include <cuda_runtime.h>
#include <math.h>

#define BATCH 256
#define NA 8192
#define NE 262144
#define NACT 21
#define LOG2E 1.4426950408889634f
#define LN2   0.6931471805599453f

// ---------------- scratch (device globals; no allocs allowed) ----------------
__device__ float g_c1[BATCH * 1152];   // [256,32,6,6]
__device__ float g_c2[BATCH * 1024];   // [256,64,4,4] flattened
__device__ float g_hidden[BATCH * 512];
__device__ float g_ae0[NA];
__device__ float g_dinv[NA];
__device__ int   g_deg[NA];
__device__ float g_agg[NA * 16];
__device__ float g_agg2[NA * 16];
__device__ float g_w2t[NA * 16];   // gcn2_w^T, pre-scaled by LOG2E
__device__ float g_b2l[NA];        // gcn2_b * LOG2E
__device__ float g_colsum[16];     // LOG2E * column sums of gcn2_w (over j)
__device__ float g_sumb2l;         // LOG2E * sum of gcn2_b

__device__ __forceinline__ float fexp2(float x) {
    float y; asm("ex2.approx.ftz.f32 %0, %1;" : "=f"(y) : "f"(x)); return y;
}
__device__ __forceinline__ float flog2(float x) {
    float y; asm("lg2.approx.ftz.f32 %0, %1;" : "=f"(y) : "f"(x)); return y;
}
__device__ __forceinline__ void red4(float* p, float a, float b, float c, float d) {
    asm volatile("red.global.add.v4.f32 [%0], {%1,%2,%3,%4};"
                 :: "l"(p), "f"(a), "f"(b), "f"(c), "f"(d) : "memory");
}
__device__ __forceinline__ unsigned long long ffma2(unsigned long long a,
                                                    unsigned long long b,
                                                    unsigned long long c) {
    unsigned long long d;
    asm("fma.rn.f32x2 %0, %1, %2, %3;" : "=l"(d) : "l"(a), "l"(b), "l"(c));
    return d;
}
__device__ __forceinline__ unsigned long long packf2(float lo, float hi) {
    unsigned long long r;
    asm("mov.b64 %0, {%1,%2};" : "=l"(r) : "f"(lo), "f"(hi));
    return r;
}
__device__ __forceinline__ void unpackf2(unsigned long long v, float& lo, float& hi) {
    asm("mov.b64 {%0,%1}, %2;" : "=f"(lo), "=f"(hi) : "l"(v));
}

// ---------------- conv1: smem-staged, 5 independent acc chains (ILP) --------
__global__ void __launch_bounds__(256) conv1_kernel(const float* __restrict__ x,
                                                    const float* __restrict__ w,
                                                    const float* __restrict__ b) {
    __shared__ float xs[845];    // 5*13*13
    __shared__ float ws[1440];   // 32*45
    __shared__ float bs[32];
    int bb = blockIdx.x, t = threadIdx.x;
    for (int i = t; i < 845; i += 256) xs[i] = x[bb * 845 + i];
    for (int i = t; i < 1440; i += 256) ws[i] = w[i];
    if (t < 32) bs[t] = b[t];
    __syncthreads();
    for (int o = t; o < 1152; o += 256) {
        int oc = o / 36, r = o % 36, oy = r / 6, ox = r % 6;
        const float* wp = ws + oc * 45;
        const float* xp = xs + 2 * oy * 13 + 2 * ox;
        float a[5];
#pragma unroll
        for (int ic = 0; ic < 5; ic++) {
            a[ic] = 0.f;
#pragma unroll
            for (int ky = 0; ky < 3; ky++)
#pragma unroll
                for (int kx = 0; kx < 3; kx++)
                    a[ic] += xp[ic * 169 + ky * 13 + kx] * wp[ic * 9 + ky * 3 + kx];
        }
        float acc = bs[oc] + (((a[0] + a[1]) + (a[2] + a[3])) + a[4]);
        g_c1[bb * 1152 + o] = fmaxf(acc, 0.f);
    }
}

// ---------------- conv2 as implicit GEMM: [32 rows x 64 oc] x K=288 --------
__global__ void __launch_bounds__(256) conv2_kernel(const float* __restrict__ w,
                                                    const float* __restrict__ b) {
    __shared__ float imgs[2 * 1152];
    __shared__ __align__(16) float2 As2[16][33];  // [kk][row] duplicated (a,a)
    __shared__ __align__(16) float Bs[16][66];    // [kk][oc]
    int bb0 = blockIdx.x * 2;
    int tid = threadIdx.x;
    for (int i = tid; i < 2304; i += 256) imgs[i] = g_c1[bb0 * 1152 + i];

    int tx = tid & 15, ty = tid >> 4;
    int l_row = tid & 31;
    int l_kk0 = (tid >> 5) * 2;
    int l_pos = l_row & 15;
    int l_base = (l_row >> 4) * 1152 + (l_pos >> 2) * 6 + (l_pos & 3);
    int b_oc = tid & 63;
    int b_kk0 = (tid >> 6) * 4;

    unsigned long long acc00 = 0, acc01 = 0, acc10 = 0, acc11 = 0;

    for (int k0 = 0; k0 < 288; k0 += 16) {
        __syncthreads();
        float4 wv = *(const float4*)(w + b_oc * 288 + k0 + b_kk0);
        Bs[b_kk0][b_oc]     = wv.x;
        Bs[b_kk0 + 1][b_oc] = wv.y;
        Bs[b_kk0 + 2][b_oc] = wv.z;
        Bs[b_kk0 + 3][b_oc] = wv.w;
#pragma unroll
        for (int u = 0; u < 2; u++) {
            int k = k0 + l_kk0 + u;
            int ic = (k * 57) >> 9;
            int r9 = k - ic * 9;
            int ky = (r9 * 11) >> 5;
            int kx = r9 - ky * 3;
            float v = imgs[l_base + ic * 36 + ky * 6 + kx];
            As2[l_kk0 + u][l_row] = make_float2(v, v);
        }
        __syncthreads();
#pragma unroll
        for (int kk = 0; kk < 16; kk++) {
            unsigned long long a0 = *(const unsigned long long*)&As2[kk][ty * 2];
            unsigned long long a1 = *(const unsigned long long*)&As2[kk][ty * 2 + 1];
            unsigned long long bp0 = *(const unsigned long long*)&Bs[kk][tx * 4];
            unsigned long long bp1 = *(const unsigned long long*)&Bs[kk][tx * 4 + 2];
            acc00 = ffma2(a0, bp0, acc00);
            acc01 = ffma2(a0, bp1, acc01);
            acc10 = ffma2(a1, bp0, acc10);
            acc11 = ffma2(a1, bp1, acc11);
        }
    }

    int c = tx * 4;
    float4 bv = *(const float4*)(b + c);
    float v00, v01, v02, v03, v10, v11, v12, v13;
    unpackf2(acc00, v00, v01);
    unpackf2(acc01, v02, v03);
    unpackf2(acc10, v10, v11);
    unpackf2(acc11, v12, v13);
    int r0 = ty * 2;
    int bi = r0 >> 4;
    int pos0 = r0 & 15, pos1 = pos0 + 1;
    float* o0 = g_c2 + (bb0 + bi) * 1024 + pos0;
    float* o1 = g_c2 + (bb0 + bi) * 1024 + pos1;
    o0[(c + 0) * 16] = fmaxf(v00 + bv.x, 0.f);
    o0[(c + 1) * 16] = fmaxf(v01 + bv.y, 0.f);
    o0[(c + 2) * 16] = fmaxf(v02 + bv.z, 0.f);
    o0[(c + 3) * 16] = fmaxf(v03 + bv.w, 0.f);
    o1[(c + 0) * 16] = fmaxf(v10 + bv.x, 0.f);
    o1[(c + 1) * 16] = fmaxf(v11 + bv.y, 0.f);
    o1[(c + 2) * 16] = fmaxf(v12 + bv.z, 0.f);
    o1[(c + 3) * 16] = fmaxf(v13 + bv.w, 0.f);
}

// ---------------- FC: 32x32 tiles, 2x2 microtile, f32x2 FFMA2 --------------
__global__ void __launch_bounds__(256) fc_kernel(const float* __restrict__ W,  // [512,1024]
                                                 const float* __restrict__ b) {
    __shared__ float2 As2[16][33];
    __shared__ float  Bs[16][34];
    int tid = threadIdx.x;
    int tx = tid & 15, ty = tid >> 4;
    int row0 = blockIdx.y * 32, col0 = blockIdx.x * 32;
    int lrow = tid >> 3;
    int lkk  = (tid & 7) * 2;
    unsigned long long acc0 = 0ULL, acc1 = 0ULL;
    for (int k0 = 0; k0 < 1024; k0 += 16) {
        float2 av = *(const float2*)(g_c2 + (row0 + lrow) * 1024 + k0 + lkk);
        float2 bv = *(const float2*)(W + (col0 + lrow) * 1024 + k0 + lkk);
        As2[lkk][lrow]     = make_float2(av.x, av.x);
        As2[lkk + 1][lrow] = make_float2(av.y, av.y);
        Bs[lkk][lrow]      = bv.x;
        Bs[lkk + 1][lrow]  = bv.y;
        __syncthreads();
#pragma unroll
        for (int kk = 0; kk < 16; kk++) {
            unsigned long long a0 = *(const unsigned long long*)&As2[kk][ty * 2];
            unsigned long long a1 = *(const unsigned long long*)&As2[kk][ty * 2 + 1];
            unsigned long long bp = *(const unsigned long long*)&Bs[kk][tx * 2];
            acc0 = ffma2(a0, bp, acc0);
            acc1 = ffma2(a1, bp, acc1);
        }
        __syncthreads();
    }
    float o00, o01, o10, o11;
    unpackf2(acc0, o00, o01);
    unpackf2(acc1, o10, o11);
    int r0 = row0 + ty * 2, c0 = col0 + tx * 2;
    float b0 = b[c0], b1 = b[c0 + 1];
    g_hidden[r0 * 512 + c0]           = fmaxf(o00 + b0, 0.f);
    g_hidden[r0 * 512 + c0 + 1]       = fmaxf(o01 + b1, 0.f);
    g_hidden[(r0 + 1) * 512 + c0]     = fmaxf(o10 + b0, 0.f);
    g_hidden[(r0 + 1) * 512 + c0 + 1] = fmaxf(o11 + b1, 0.f);
}

// ---------------- logits + log_prob + entropy + action passthrough ----------
__global__ void logits_kernel(const float* __restrict__ Wmu,  // [21,512]
                              const float* __restrict__ bmu,
                              const int* __restrict__ action,
                              float* __restrict__ out_act,
                              float* __restrict__ lp_out,
                              float* __restrict__ ent_out) {
    __shared__ float lg[NACT];
    int bb = blockIdx.x;
    int lane = threadIdx.x;
    const float* h = g_hidden + bb * 512;
    float hreg[16];
#pragma unroll
    for (int i = 0; i < 16; i++) hreg[i] = h[lane + 32 * i];
    for (int o = 0; o < NACT; o++) {
        const float* wr = Wmu + o * 512;
        float acc = 0.f;
#pragma unroll
        for (int i = 0; i < 16; i++) acc += hreg[i] * wr[lane + 32 * i];
#pragma unroll
        for (int off = 16; off; off >>= 1) acc += __shfl_down_sync(0xffffffffu, acc, off);
        if (lane == 0) lg[o] = acc + bmu[o];
    }
    __syncwarp();
    if (lane == 0) {
        float m = -1e30f;
        for (int o = 0; o < NACT; o++) m = fmaxf(m, lg[o]);
        float s = 0.f;
        for (int o = 0; o < NACT; o++) s += expf(lg[o] - m);
        float lse = m + logf(s);
        float ent = 0.f;
        for (int o = 0; o < NACT; o++) {
            float lpo = lg[o] - lse;
            ent -= expf(lpo) * lpo;
        }
        lp_out[bb] = lg[action[bb]] - lse;
        ent_out[bb] = ent;
        out_act[bb] = (float)action[bb];
    }
}

// ---------------- actor_encoding row 0: GEMV (float4) -----------------------
__global__ void __launch_bounds__(256) ae0_kernel(const float* __restrict__ Wm,
                                                  const float* __restrict__ bm) {
    int wid = (blockIdx.x * blockDim.x + threadIdx.x) >> 5;
    int lane = threadIdx.x & 31;
    if (wid >= NA) return;
    const float4* wr = (const float4*)(Wm + wid * 512);
    const float4* hp = (const float4*)g_hidden;
    float acc = 0.f;
#pragma unroll
    for (int i = 0; i < 4; i++) {
        float4 w = wr[lane + 32 * i];
        float4 h = hp[lane + 32 * i];
        acc += w.x * h.x + w.y * h.y + w.z * h.z + w.w * h.w;
    }
#pragma unroll
    for (int off = 16; off; off >>= 1) acc += __shfl_down_sync(0xffffffffu, acc, off);
    if (lane == 0) g_ae0[wid] = acc + bm[wid];
}

// ---------------- graph prep ------------------------------------------------
__global__ void deg_kernel(const int* __restrict__ edge) {
    int idx = blockIdx.x * blockDim.x + threadIdx.x;
    if (idx >= NE) return;
    atomicAdd(&g_deg[edge[2 * idx + 1]], 1);
}

// dinv + b2l (idx<NA); transpose gcn2_w with LOG2E pre-scale; zero agg/agg2
__global__ void dinv_w2t_kernel(const float* __restrict__ w2,   // [16, 8192]
                                const float* __restrict__ b2) {
    int idx = blockIdx.x * blockDim.x + threadIdx.x;
    if (idx < NA) {
        g_dinv[idx] = rsqrtf((float)(g_deg[idx] + 1));  // +1 self-loop
        g_b2l[idx] = b2[idx] * LOG2E;
    }
    if (idx >= NA * 16) return;
    g_agg[idx] = 0.f;
    g_agg2[idx] = 0.f;
    int j = idx % NA, k = idx / NA;
    g_w2t[j * 16 + k] = w2[k * NA + j] * LOG2E;
}

// column sums of w2 + sum of b2, scaled by LOG2E (one block per row)
__global__ void __launch_bounds__(256) colsum_kernel(const float* __restrict__ w2,
                                                     const float* __restrict__ b2) {
    __shared__ float red[8];
    int row = blockIdx.x;
    int tid = threadIdx.x, lane = tid & 31, warp = tid >> 5;
    const float* src = (row < 16) ? (w2 + row * NA) : b2;
    const float4* p = (const float4*)src;
    float s = 0.f;
    for (int i = tid; i < NA / 4; i += 256) {
        float4 v = p[i];
        s += v.x + v.y + v.z + v.w;
    }
#pragma unroll
    for (int off = 16; off; off >>= 1) s += __shfl_down_sync(0xffffffffu, s, off);
    if (lane == 0) red[warp] = s;
    __syncthreads();
    if (tid == 0) {
        float t = 0.f;
#pragma unroll
        for (int w = 0; w < 8; w++) t += red[w];
        if (row < 16) g_colsum[row] = t * LOG2E;
        else g_sumb2l = t * LOG2E;
    }
}

// ------- scatter1 (fused feats@gcn1_w): agg[dst] += norm * (feat(src)@W1) ---
__global__ void scatter1_kernel(const float* __restrict__ x_msg,
                                const int* __restrict__ edge,
                                const float* __restrict__ w1) {  // [2,16]
    __shared__ float w1s[32];
    if (threadIdx.x < 32) w1s[threadIdx.x] = w1[threadIdx.x];
    __syncthreads();
    int e = blockIdx.x * blockDim.x + threadIdx.x;
    if (e >= NE + NA) return;
    int src, dst; float norm;
    if (e < NE) {
        int2 ed = ((const int2*)edge)[e];
        src = ed.x; dst = ed.y;
        norm = g_dinv[src] * g_dinv[dst];
    } else {
        src = dst = e - NE;
        float d = g_dinv[src];
        norm = d * d;
    }
    float f0 = x_msg[src] * norm;
    float f1 = g_ae0[src] * norm;
    float* out = g_agg + dst * 16;
    float h[16];
#pragma unroll
    for (int k = 0; k < 16; k++) h[k] = f0 * w1s[k] + f1 * w1s[16 + k];
    red4(out +  0, h[0],  h[1],  h[2],  h[3]);
    red4(out +  4, h[4],  h[5],  h[6],  h[7]);
    red4(out +  8, h[8],  h[9],  h[10], h[11]);
    red4(out + 12, h[12], h[13], h[14], h[15]);
}

// ------- scatter2 (fused relu+bias): agg2[dst] += norm * relu(agg[src]+b1) --
__global__ void scatter2_kernel(const int* __restrict__ edge,
                                const float* __restrict__ b1) {  // [16]
    __shared__ float b1s[16];
    if (threadIdx.x < 16) b1s[threadIdx.x] = b1[threadIdx.x];
    __syncthreads();
    int e = blockIdx.x * blockDim.x + threadIdx.x;
    if (e >= NE + NA) return;
    int src, dst; float norm;
    if (e < NE) {
        int2 ed = ((const int2*)edge)[e];
        src = ed.x; dst = ed.y;
        norm = g_dinv[src] * g_dinv[dst];
    } else {
        src = dst = e - NE;
        float d = g_dinv[src];
        norm = d * d;
    }
    const float4* in = (const float4*)(g_agg + src * 16);
    float* out = g_agg2 + dst * 16;
    float h[16];
#pragma unroll
    for (int q = 0; q < 4; q++) {
        float4 v = in[q];
        h[4 * q + 0] = fmaxf(v.x + b1s[4 * q + 0], 0.f) * norm;
        h[4 * q + 1] = fmaxf(v.y + b1s[4 * q + 1], 0.f) * norm;
        h[4 * q + 2] = fmaxf(v.z + b1s[4 * q + 2], 0.f) * norm;
        h[4 * q + 3] = fmaxf(v.w + b1s[4 * q + 3], 0.f) * norm;
    }
    red4(out +  0, h[0],  h[1],  h[2],  h[3]);
    red4(out +  4, h[4],  h[5],  h[6],  h[7]);
    red4(out +  8, h[8],  h[9],  h[10], h[11]);
    red4(out + 12, h[12], h[13], h[14], h[15]);
}

// ---------------- fused g2-row GEMM + log_softmax mean ----------------------
#define RPB 16
__global__ void __launch_bounds__(256)
rows_kernel(float* __restrict__ out) {
    __shared__ __align__(16) float aS[RPB][16];
    __shared__ float redse[8][RPB];
    int tid = threadIdx.x;
    int i0 = blockIdx.x * RPB;
    aS[tid >> 4][tid & 15] = g_agg2[i0 * 16 + tid];
    __syncthreads();

    float se[RPB];
#pragma unroll
    for (int r = 0; r < RPB; r++) se[r] = 0.f;

#pragma unroll 2
    for (int j = tid; j < NA; j += 256) {
        const ulonglong2* wp = (const ulonglong2*)(g_w2t + j * 16);
        ulonglong2 w0 = wp[0], w1 = wp[1], w2 = wp[2], w3 = wp[3];
        unsigned long long binit = packf2(g_b2l[j], 0.f);
#pragma unroll
        for (int r = 0; r < RPB; r++) {
            const ulonglong2* ap = (const ulonglong2*)aS[r];
            ulonglong2 a0 = ap[0], a1 = ap[1], a2 = ap[2], a3 = ap[3];
            unsigned long long acc = binit;
            acc = ffma2(a0.x, w0.x, acc);
            acc = ffma2(a0.y, w0.y, acc);
            acc = ffma2(a1.x, w1.x, acc);
            acc = ffma2(a1.y, w1.y, acc);
            acc = ffma2(a2.x, w2.x, acc);
            acc = ffma2(a2.y, w2.y, acc);
            acc = ffma2(a3.x, w3.x, acc);
            acc = ffma2(a3.y, w3.y, acc);
            float lo, hi;
            unpackf2(acc, lo, hi);
            se[r] += fexp2(lo + hi);
        }
    }

    int lane = tid & 31, warp = tid >> 5;
#pragma unroll
    for (int off = 16; off; off >>= 1) {
#pragma unroll
        for (int r = 0; r < RPB; r++)
            se[r] += __shfl_down_sync(0xffffffffu, se[r], off);
    }
    if (lane == 0) {
#pragma unroll
        for (int r = 0; r < RPB; r++) redse[warp][r] = se[r];
    }
    __syncthreads();
    if (tid < RPB) {
        int r = tid;
        float s = 0.f;
#pragma unroll
        for (int w = 0; w < 8; w++) s += redse[w][r];
        float mean = g_sumb2l;
#pragma unroll
        for (int k = 0; k < 16; k++) mean += aS[r][k] * g_colsum[k];
        out[i0 + r] = LN2 * (mean * (1.f / (float)NA) - flog2(s));
    }
}

// ---------------- launch -----------------------------------------------------
extern "C" void kernel_launch(void* const* d_in, const int* in_sizes, int n_in,
                              void* d_out, int out_size) {
    const float* x       = (const float*)d_in[0];
    const float* x_msg   = (const float*)d_in[1];
    const int*   edge    = (const int*)d_in[2];
    const int*   action  = (const int*)d_in[3];
    const float* conv1_w = (const float*)d_in[4];
    const float* conv1_b = (const float*)d_in[5];
    const float* conv2_w = (const float*)d_in[6];
    const float* conv2_b = (const float*)d_in[7];
    const float* fc_w    = (const float*)d_in[8];
    const float* fc_b    = (const float*)d_in[9];
    const float* fcmu_w  = (const float*)d_in[10];
    const float* fcmu_b  = (const float*)d_in[11];
    const float* msg_w   = (const float*)d_in[12];
    const float* msg_b   = (const float*)d_in[13];
    const float* gcn1_w  = (const float*)d_in[14];
    const float* gcn1_b  = (const float*)d_in[15];
    const float* gcn2_w  = (const float*)d_in[16];
    const float* gcn2_b  = (const float*)d_in[17];

    float* out = (float*)d_out;
    float* out_msg = out + BATCH;
    float* out_lp  = out + BATCH + NA;
    float* out_ent = out + BATCH + NA + BATCH;

    void* p_deg;
    cudaGetSymbolAddress(&p_deg, g_deg);
    cudaMemsetAsync(p_deg, 0, NA * sizeof(int));

    deg_kernel<<<(NE + 255) / 256, 256>>>(edge);                         // k1
    dinv_w2t_kernel<<<(NA * 16 + 255) / 256, 256>>>(gcn2_w, gcn2_b);     // k2
    conv1_kernel<<<BATCH, 256>>>(x, conv1_w, conv1_b);                   // k3
    conv2_kernel<<<BATCH / 2, 256>>>(conv2_w, conv2_b);                  // k4 <- profiled
    colsum_kernel<<<17, 256>>>(gcn2_w, gcn2_b);                          // k5
    fc_kernel<<<dim3(16, 8), 256>>>(fc_w, fc_b);
    logits_kernel<<<BATCH, 32>>>(fcmu_w, fcmu_b, action, out, out_lp, out_ent);
    ae0_kernel<<<NA * 32 / 256, 256>>>(msg_w, msg_b);

    scatter1_kernel<<<(NE + NA + 255) / 256, 256>>>(x_msg, edge, gcn1_w);
    scatter2_kernel<<<(NE + NA + 255) / 256, 256>>>(edge, gcn1_b);
    rows_kernel<<<NA / RPB, 256>>>(out_msg);
}

// round 8
// speedup vs baseline: 1.2654x; 1.0353x over previous
#include <cuda_runtime.h>
#include <math.h>

#define BATCH 256
#define NA 8192
#define NE 262144
#define NACT 21
#define LOG2E 1.4426950408889634f
#define LN2   0.6931471805599453f

// ---------------- scratch (device globals; no allocs allowed) ----------------
__device__ float g_c1[BATCH * 1152];   // [256,32,6,6]
__device__ float g_c2[BATCH * 1024];   // [256,64,4,4] flattened
__device__ float g_hidden[BATCH * 512];
__device__ float g_ae0[NA];
__device__ float g_dinv[NA];
__device__ int   g_deg[NA];
__device__ float g_agg[NA * 16];
__device__ float g_agg2[NA * 16];
__device__ float g_w2t[NA * 16];   // gcn2_w^T, pre-scaled by LOG2E
__device__ float g_b2l[NA];        // gcn2_b * LOG2E
__device__ float g_colsum[16];     // LOG2E * column sums of gcn2_w (over j)
__device__ float g_sumb2l;         // LOG2E * sum of gcn2_b

__device__ __forceinline__ float fexp2(float x) {
    float y; asm("ex2.approx.ftz.f32 %0, %1;" : "=f"(y) : "f"(x)); return y;
}
__device__ __forceinline__ float flog2(float x) {
    float y; asm("lg2.approx.ftz.f32 %0, %1;" : "=f"(y) : "f"(x)); return y;
}
__device__ __forceinline__ void red4(float* p, float a, float b, float c, float d) {
    asm volatile("red.global.add.v4.f32 [%0], {%1,%2,%3,%4};"
                 :: "l"(p), "f"(a), "f"(b), "f"(c), "f"(d) : "memory");
}
__device__ __forceinline__ unsigned long long ffma2(unsigned long long a,
                                                    unsigned long long b,
                                                    unsigned long long c) {
    unsigned long long d;
    asm("fma.rn.f32x2 %0, %1, %2, %3;" : "=l"(d) : "l"(a), "l"(b), "l"(c));
    return d;
}
__device__ __forceinline__ unsigned long long packf2(float lo, float hi) {
    unsigned long long r;
    asm("mov.b64 %0, {%1,%2};" : "=l"(r) : "f"(lo), "f"(hi));
    return r;
}
__device__ __forceinline__ void unpackf2(unsigned long long v, float& lo, float& hi) {
    asm("mov.b64 {%0,%1}, %2;" : "=f"(lo), "=f"(hi) : "l"(v));
}

// ---------------- conv1: smem-staged, 5 independent acc chains (ILP) --------
__global__ void __launch_bounds__(256) conv1_kernel(const float* __restrict__ x,
                                                    const float* __restrict__ w,
                                                    const float* __restrict__ b) {
    __shared__ float xs[845];    // 5*13*13
    __shared__ float ws[1440];   // 32*45
    __shared__ float bs[32];
    int bb = blockIdx.x, t = threadIdx.x;
    for (int i = t; i < 845; i += 256) xs[i] = x[bb * 845 + i];
    for (int i = t; i < 1440; i += 256) ws[i] = w[i];
    if (t < 32) bs[t] = b[t];
    __syncthreads();
    for (int o = t; o < 1152; o += 256) {
        int oc = o / 36, r = o % 36, oy = r / 6, ox = r % 6;
        const float* wp = ws + oc * 45;
        const float* xp = xs + 2 * oy * 13 + 2 * ox;
        float a[5];
#pragma unroll
        for (int ic = 0; ic < 5; ic++) {
            a[ic] = 0.f;
#pragma unroll
            for (int ky = 0; ky < 3; ky++)
#pragma unroll
                for (int kx = 0; kx < 3; kx++)
                    a[ic] += xp[ic * 169 + ky * 13 + kx] * wp[ic * 9 + ky * 3 + kx];
        }
        float acc = bs[oc] + (((a[0] + a[1]) + (a[2] + a[3])) + a[4]);
        g_c1[bb * 1152 + o] = fmaxf(acc, 0.f);
    }
}

// ---------------- conv2: direct conv, 2x2 quadrant per thread ---------------
// grid = 128 batch-pairs x 2 oc-halves; block: bi(2) x oc(32) x quad(4) = 256
// weights for the oc-half staged in smem with stride 292 (bank-conflict-free)
#define WST 292
__global__ void __launch_bounds__(256) conv2_kernel(const float* __restrict__ w,
                                                    const float* __restrict__ b) {
    __shared__ float ws[32 * WST];      // ~36.5KB
    __shared__ float imgs[2 * 1152];    // 9.2KB
    int bp = blockIdx.x >> 1;
    int oh = blockIdx.x & 1;
    int bb0 = bp * 2;
    int tid = threadIdx.x;

    // stage weights: contiguous half [32][288] -> padded stride WST
    const float4* wsrc = (const float4*)(w + oh * 9216);
    for (int i4 = tid; i4 < 2304; i4 += 256) {
        int o = i4 / 72, k4 = i4 % 72;
        *(float4*)(ws + o * WST + k4 * 4) = wsrc[i4];
    }
    // stage 2 input images
    {
        const float4* isrc = (const float4*)(g_c1 + bb0 * 1152);
        float4* idst = (float4*)imgs;
        for (int i = tid; i < 576; i += 256) idst[i] = isrc[i];
    }
    __syncthreads();

    int bi = tid >> 7;
    int oc = (tid >> 2) & 31;
    int qy = (tid >> 1) & 1, qx = tid & 1;
    const float* wp = ws + oc * WST;
    const float* ip = imgs + bi * 1152 + 2 * qy * 6 + 2 * qx;

    float a00 = 0.f, a01 = 0.f, a10 = 0.f, a11 = 0.f;
    for (int ic = 0; ic < 32; ic++) {
        float wr[9];
#pragma unroll
        for (int k = 0; k < 9; k++) wr[k] = wp[ic * 9 + k];
        float im[4][4];
#pragma unroll
        for (int r = 0; r < 4; r++) {
            float2 v0 = *(const float2*)(ip + ic * 36 + r * 6);
            float2 v1 = *(const float2*)(ip + ic * 36 + r * 6 + 2);
            im[r][0] = v0.x; im[r][1] = v0.y; im[r][2] = v1.x; im[r][3] = v1.y;
        }
#pragma unroll
        for (int ky = 0; ky < 3; ky++)
#pragma unroll
            for (int kx = 0; kx < 3; kx++) {
                float wv = wr[ky * 3 + kx];
                a00 += im[ky][kx] * wv;
                a01 += im[ky][kx + 1] * wv;
                a10 += im[ky + 1][kx] * wv;
                a11 += im[ky + 1][kx + 1] * wv;
            }
    }
    int ocg = oh * 32 + oc;
    float bias = b[ocg];
    float* op = g_c2 + (bb0 + bi) * 1024 + ocg * 16 + 2 * qy * 4 + 2 * qx;
    op[0] = fmaxf(a00 + bias, 0.f);
    op[1] = fmaxf(a01 + bias, 0.f);
    op[4] = fmaxf(a10 + bias, 0.f);
    op[5] = fmaxf(a11 + bias, 0.f);
}

// ---------------- FC: 32x32 tiles, 2x2 microtile, f32x2 FFMA2 --------------
__global__ void __launch_bounds__(256) fc_kernel(const float* __restrict__ W,  // [512,1024]
                                                 const float* __restrict__ b) {
    __shared__ float2 As2[16][33];
    __shared__ float  Bs[16][34];
    int tid = threadIdx.x;
    int tx = tid & 15, ty = tid >> 4;
    int row0 = blockIdx.y * 32, col0 = blockIdx.x * 32;
    int lrow = tid >> 3;
    int lkk  = (tid & 7) * 2;
    unsigned long long acc0 = 0ULL, acc1 = 0ULL;
    for (int k0 = 0; k0 < 1024; k0 += 16) {
        float2 av = *(const float2*)(g_c2 + (row0 + lrow) * 1024 + k0 + lkk);
        float2 bv = *(const float2*)(W + (col0 + lrow) * 1024 + k0 + lkk);
        As2[lkk][lrow]     = make_float2(av.x, av.x);
        As2[lkk + 1][lrow] = make_float2(av.y, av.y);
        Bs[lkk][lrow]      = bv.x;
        Bs[lkk + 1][lrow]  = bv.y;
        __syncthreads();
#pragma unroll
        for (int kk = 0; kk < 16; kk++) {
            unsigned long long a0 = *(const unsigned long long*)&As2[kk][ty * 2];
            unsigned long long a1 = *(const unsigned long long*)&As2[kk][ty * 2 + 1];
            unsigned long long bp = *(const unsigned long long*)&Bs[kk][tx * 2];
            acc0 = ffma2(a0, bp, acc0);
            acc1 = ffma2(a1, bp, acc1);
        }
        __syncthreads();
    }
    float o00, o01, o10, o11;
    unpackf2(acc0, o00, o01);
    unpackf2(acc1, o10, o11);
    int r0 = row0 + ty * 2, c0 = col0 + tx * 2;
    float b0 = b[c0], b1 = b[c0 + 1];
    g_hidden[r0 * 512 + c0]           = fmaxf(o00 + b0, 0.f);
    g_hidden[r0 * 512 + c0 + 1]       = fmaxf(o01 + b1, 0.f);
    g_hidden[(r0 + 1) * 512 + c0]     = fmaxf(o10 + b0, 0.f);
    g_hidden[(r0 + 1) * 512 + c0 + 1] = fmaxf(o11 + b1, 0.f);
}

// ---------------- logits + log_prob + entropy + action passthrough ----------
__global__ void logits_kernel(const float* __restrict__ Wmu,  // [21,512]
                              const float* __restrict__ bmu,
                              const int* __restrict__ action,
                              float* __restrict__ out_act,
                              float* __restrict__ lp_out,
                              float* __restrict__ ent_out) {
    __shared__ float lg[NACT];
    int bb = blockIdx.x;
    int lane = threadIdx.x;
    const float* h = g_hidden + bb * 512;
    float hreg[16];
#pragma unroll
    for (int i = 0; i < 16; i++) hreg[i] = h[lane + 32 * i];
    for (int o = 0; o < NACT; o++) {
        const float* wr = Wmu + o * 512;
        float acc = 0.f;
#pragma unroll
        for (int i = 0; i < 16; i++) acc += hreg[i] * wr[lane + 32 * i];
#pragma unroll
        for (int off = 16; off; off >>= 1) acc += __shfl_down_sync(0xffffffffu, acc, off);
        if (lane == 0) lg[o] = acc + bmu[o];
    }
    __syncwarp();
    if (lane == 0) {
        float m = -1e30f;
        for (int o = 0; o < NACT; o++) m = fmaxf(m, lg[o]);
        float s = 0.f;
        for (int o = 0; o < NACT; o++) s += expf(lg[o] - m);
        float lse = m + logf(s);
        float ent = 0.f;
        for (int o = 0; o < NACT; o++) {
            float lpo = lg[o] - lse;
            ent -= expf(lpo) * lpo;
        }
        lp_out[bb] = lg[action[bb]] - lse;
        ent_out[bb] = ent;
        out_act[bb] = (float)action[bb];
    }
}

// ---------------- actor_encoding row 0: GEMV (float4) -----------------------
__global__ void __launch_bounds__(256) ae0_kernel(const float* __restrict__ Wm,
                                                  const float* __restrict__ bm) {
    int wid = (blockIdx.x * blockDim.x + threadIdx.x) >> 5;
    int lane = threadIdx.x & 31;
    if (wid >= NA) return;
    const float4* wr = (const float4*)(Wm + wid * 512);
    const float4* hp = (const float4*)g_hidden;
    float acc = 0.f;
#pragma unroll
    for (int i = 0; i < 4; i++) {
        float4 w = wr[lane + 32 * i];
        float4 h = hp[lane + 32 * i];
        acc += w.x * h.x + w.y * h.y + w.z * h.z + w.w * h.w;
    }
#pragma unroll
    for (int off = 16; off; off >>= 1) acc += __shfl_down_sync(0xffffffffu, acc, off);
    if (lane == 0) g_ae0[wid] = acc + bm[wid];
}

// ---------------- graph prep ------------------------------------------------
__global__ void deg_kernel(const int* __restrict__ edge) {
    int idx = blockIdx.x * blockDim.x + threadIdx.x;
    if (idx >= NE) return;
    atomicAdd(&g_deg[edge[2 * idx + 1]], 1);
}

// dinv + b2l (idx<NA); transpose gcn2_w with LOG2E pre-scale; zero agg/agg2
__global__ void dinv_w2t_kernel(const float* __restrict__ w2,   // [16, 8192]
                                const float* __restrict__ b2) {
    int idx = blockIdx.x * blockDim.x + threadIdx.x;
    if (idx < NA) {
        g_dinv[idx] = rsqrtf((float)(g_deg[idx] + 1));  // +1 self-loop
        g_b2l[idx] = b2[idx] * LOG2E;
    }
    if (idx >= NA * 16) return;
    g_agg[idx] = 0.f;
    g_agg2[idx] = 0.f;
    int j = idx % NA, k = idx / NA;
    g_w2t[j * 16 + k] = w2[k * NA + j] * LOG2E;
}

// column sums of w2 + sum of b2, scaled by LOG2E (one block per row)
__global__ void __launch_bounds__(256) colsum_kernel(const float* __restrict__ w2,
                                                     const float* __restrict__ b2) {
    __shared__ float red[8];
    int row = blockIdx.x;
    int tid = threadIdx.x, lane = tid & 31, warp = tid >> 5;
    const float* src = (row < 16) ? (w2 + row * NA) : b2;
    const float4* p = (const float4*)src;
    float s = 0.f;
    for (int i = tid; i < NA / 4; i += 256) {
        float4 v = p[i];
        s += v.x + v.y + v.z + v.w;
    }
#pragma unroll
    for (int off = 16; off; off >>= 1) s += __shfl_down_sync(0xffffffffu, s, off);
    if (lane == 0) red[warp] = s;
    __syncthreads();
    if (tid == 0) {
        float t = 0.f;
#pragma unroll
        for (int w = 0; w < 8; w++) t += red[w];
        if (row < 16) g_colsum[row] = t * LOG2E;
        else g_sumb2l = t * LOG2E;
    }
}

// ------- scatter1 (fused feats@gcn1_w): agg[dst] += norm * (feat(src)@W1) ---
__global__ void scatter1_kernel(const float* __restrict__ x_msg,
                                const int* __restrict__ edge,
                                const float* __restrict__ w1) {  // [2,16]
    __shared__ float w1s[32];
    if (threadIdx.x < 32) w1s[threadIdx.x] = w1[threadIdx.x];
    __syncthreads();
    int e = blockIdx.x * blockDim.x + threadIdx.x;
    if (e >= NE + NA) return;
    int src, dst; float norm;
    if (e < NE) {
        int2 ed = ((const int2*)edge)[e];
        src = ed.x; dst = ed.y;
        norm = g_dinv[src] * g_dinv[dst];
    } else {
        src = dst = e - NE;
        float d = g_dinv[src];
        norm = d * d;
    }
    float f0 = x_msg[src] * norm;
    float f1 = g_ae0[src] * norm;
    float* out = g_agg + dst * 16;
    float h[16];
#pragma unroll
    for (int k = 0; k < 16; k++) h[k] = f0 * w1s[k] + f1 * w1s[16 + k];
    red4(out +  0, h[0],  h[1],  h[2],  h[3]);
    red4(out +  4, h[4],  h[5],  h[6],  h[7]);
    red4(out +  8, h[8],  h[9],  h[10], h[11]);
    red4(out + 12, h[12], h[13], h[14], h[15]);
}

// ------- scatter2 (fused relu+bias): agg2[dst] += norm * relu(agg[src]+b1) --
__global__ void scatter2_kernel(const int* __restrict__ edge,
                                const float* __restrict__ b1) {  // [16]
    __shared__ float b1s[16];
    if (threadIdx.x < 16) b1s[threadIdx.x] = b1[threadIdx.x];
    __syncthreads();
    int e = blockIdx.x * blockDim.x + threadIdx.x;
    if (e >= NE + NA) return;
    int src, dst; float norm;
    if (e < NE) {
        int2 ed = ((const int2*)edge)[e];
        src = ed.x; dst = ed.y;
        norm = g_dinv[src] * g_dinv[dst];
    } else {
        src = dst = e - NE;
        float d = g_dinv[src];
        norm = d * d;
    }
    const float4* in = (const float4*)(g_agg + src * 16);
    float* out = g_agg2 + dst * 16;
    float h[16];
#pragma unroll
    for (int q = 0; q < 4; q++) {
        float4 v = in[q];
        h[4 * q + 0] = fmaxf(v.x + b1s[4 * q + 0], 0.f) * norm;
        h[4 * q + 1] = fmaxf(v.y + b1s[4 * q + 1], 0.f) * norm;
        h[4 * q + 2] = fmaxf(v.z + b1s[4 * q + 2], 0.f) * norm;
        h[4 * q + 3] = fmaxf(v.w + b1s[4 * q + 3], 0.f) * norm;
    }
    red4(out +  0, h[0],  h[1],  h[2],  h[3]);
    red4(out +  4, h[4],  h[5],  h[6],  h[7]);
    red4(out +  8, h[8],  h[9],  h[10], h[11]);
    red4(out + 12, h[12], h[13], h[14], h[15]);
}

// ---------------- fused g2-row GEMM + log_softmax mean ----------------------
#define RPB 16
__global__ void __launch_bounds__(256)
rows_kernel(float* __restrict__ out) {
    __shared__ __align__(16) float aS[RPB][16];
    __shared__ float redse[8][RPB];
    int tid = threadIdx.x;
    int i0 = blockIdx.x * RPB;
    aS[tid >> 4][tid & 15] = g_agg2[i0 * 16 + tid];
    __syncthreads();

    float se[RPB];
#pragma unroll
    for (int r = 0; r < RPB; r++) se[r] = 0.f;

#pragma unroll 2
    for (int j = tid; j < NA; j += 256) {
        const ulonglong2* wp = (const ulonglong2*)(g_w2t + j * 16);
        ulonglong2 w0 = wp[0], w1 = wp[1], w2 = wp[2], w3 = wp[3];
        unsigned long long binit = packf2(g_b2l[j], 0.f);
#pragma unroll
        for (int r = 0; r < RPB; r++) {
            const ulonglong2* ap = (const ulonglong2*)aS[r];
            ulonglong2 a0 = ap[0], a1 = ap[1], a2 = ap[2], a3 = ap[3];
            unsigned long long acc = binit;
            acc = ffma2(a0.x, w0.x, acc);
            acc = ffma2(a0.y, w0.y, acc);
            acc = ffma2(a1.x, w1.x, acc);
            acc = ffma2(a1.y, w1.y, acc);
            acc = ffma2(a2.x, w2.x, acc);
            acc = ffma2(a2.y, w2.y, acc);
            acc = ffma2(a3.x, w3.x, acc);
            acc = ffma2(a3.y, w3.y, acc);
            float lo, hi;
            unpackf2(acc, lo, hi);
            se[r] += fexp2(lo + hi);
        }
    }

    int lane = tid & 31, warp = tid >> 5;
#pragma unroll
    for (int off = 16; off; off >>= 1) {
#pragma unroll
        for (int r = 0; r < RPB; r++)
            se[r] += __shfl_down_sync(0xffffffffu, se[r], off);
    }
    if (lane == 0) {
#pragma unroll
        for (int r = 0; r < RPB; r++) redse[warp][r] = se[r];
    }
    __syncthreads();
    if (tid < RPB) {
        int r = tid;
        float s = 0.f;
#pragma unroll
        for (int w = 0; w < 8; w++) s += redse[w][r];
        float mean = g_sumb2l;
#pragma unroll
        for (int k = 0; k < 16; k++) mean += aS[r][k] * g_colsum[k];
        out[i0 + r] = LN2 * (mean * (1.f / (float)NA) - flog2(s));
    }
}

// ---------------- launch -----------------------------------------------------
extern "C" void kernel_launch(void* const* d_in, const int* in_sizes, int n_in,
                              void* d_out, int out_size) {
    const float* x       = (const float*)d_in[0];
    const float* x_msg   = (const float*)d_in[1];
    const int*   edge    = (const int*)d_in[2];
    const int*   action  = (const int*)d_in[3];
    const float* conv1_w = (const float*)d_in[4];
    const float* conv1_b = (const float*)d_in[5];
    const float* conv2_w = (const float*)d_in[6];
    const float* conv2_b = (const float*)d_in[7];
    const float* fc_w    = (const float*)d_in[8];
    const float* fc_b    = (const float*)d_in[9];
    const float* fcmu_w  = (const float*)d_in[10];
    const float* fcmu_b  = (const float*)d_in[11];
    const float* msg_w   = (const float*)d_in[12];
    const float* msg_b   = (const float*)d_in[13];
    const float* gcn1_w  = (const float*)d_in[14];
    const float* gcn1_b  = (const float*)d_in[15];
    const float* gcn2_w  = (const float*)d_in[16];
    const float* gcn2_b  = (const float*)d_in[17];

    float* out = (float*)d_out;
    float* out_msg = out + BATCH;
    float* out_lp  = out + BATCH + NA;
    float* out_ent = out + BATCH + NA + BATCH;

    void* p_deg;
    cudaGetSymbolAddress(&p_deg, g_deg);
    cudaMemsetAsync(p_deg, 0, NA * sizeof(int));

    deg_kernel<<<(NE + 255) / 256, 256>>>(edge);                         // k1
    dinv_w2t_kernel<<<(NA * 16 + 255) / 256, 256>>>(gcn2_w, gcn2_b);     // k2
    conv1_kernel<<<BATCH, 256>>>(x, conv1_w, conv1_b);                   // k3
    conv2_kernel<<<BATCH, 256>>>(conv2_w, conv2_b);                      // k4 <- profiled
    colsum_kernel<<<17, 256>>>(gcn2_w, gcn2_b);                          // k5
    fc_kernel<<<dim3(16, 8), 256>>>(fc_w, fc_b);
    logits_kernel<<<BATCH, 32>>>(fcmu_w, fcmu_b, action, out, out_lp, out_ent);
    ae0_kernel<<<NA * 32 / 256, 256>>>(msg_w, msg_b);

    scatter1_kernel<<<(NE + NA + 255) / 256, 256>>>(x_msg, edge, gcn1_w);
    scatter2_kernel<<<(NE + NA + 255) / 256, 256>>>(edge, gcn1_b);
    rows_kernel<<<NA / RPB, 256>>>(out_msg);
}

// round 9
// speedup vs baseline: 1.4157x; 1.1188x over previous
#include <cuda_runtime.h>
#include <math.h>

#define BATCH 256
#define NA 8192
#define NE 262144
#define NACT 21
#define LOG2E 1.4426950408889634f
#define LN2   0.6931471805599453f

// ---------------- scratch (device globals; no allocs allowed) ----------------
__device__ float g_c1[BATCH * 1152];   // [256,32,6,6]
__device__ float g_c2[BATCH * 1024];   // [256,64,4,4] flattened
__device__ float g_hidden[BATCH * 512];
__device__ float g_ae0[NA];
__device__ float g_dinv[NA];
__device__ int   g_deg[NA];
__device__ float g_agg[NA * 16];
__device__ float g_agg2[NA * 16];
__device__ float g_w2t[NA * 16];   // gcn2_w^T, pre-scaled by LOG2E
__device__ float g_b2l[NA];        // gcn2_b * LOG2E
__device__ float g_colsum[16];     // LOG2E * column sums of gcn2_w (over j)
__device__ float g_sumb2l;         // LOG2E * sum of gcn2_b

__device__ __forceinline__ float fexp2(float x) {
    float y; asm("ex2.approx.ftz.f32 %0, %1;" : "=f"(y) : "f"(x)); return y;
}
__device__ __forceinline__ float flog2(float x) {
    float y; asm("lg2.approx.ftz.f32 %0, %1;" : "=f"(y) : "f"(x)); return y;
}
__device__ __forceinline__ void red4(float* p, float a, float b, float c, float d) {
    asm volatile("red.global.add.v4.f32 [%0], {%1,%2,%3,%4};"
                 :: "l"(p), "f"(a), "f"(b), "f"(c), "f"(d) : "memory");
}
__device__ __forceinline__ unsigned long long ffma2(unsigned long long a,
                                                    unsigned long long b,
                                                    unsigned long long c) {
    unsigned long long d;
    asm("fma.rn.f32x2 %0, %1, %2, %3;" : "=l"(d) : "l"(a), "l"(b), "l"(c));
    return d;
}
__device__ __forceinline__ unsigned long long packf2(float lo, float hi) {
    unsigned long long r;
    asm("mov.b64 %0, {%1,%2};" : "=l"(r) : "f"(lo), "f"(hi));
    return r;
}
__device__ __forceinline__ void unpackf2(unsigned long long v, float& lo, float& hi) {
    asm("mov.b64 {%0,%1}, %2;" : "=f"(lo), "=f"(hi) : "l"(v));
}

// ---------------- conv1: smem-staged, 5 independent acc chains (ILP) --------
__global__ void __launch_bounds__(256) conv1_kernel(const float* __restrict__ x,
                                                    const float* __restrict__ w,
                                                    const float* __restrict__ b) {
    __shared__ float xs[845];    // 5*13*13
    __shared__ float ws[1440];   // 32*45
    __shared__ float bs[32];
    int bb = blockIdx.x, t = threadIdx.x;
    for (int i = t; i < 845; i += 256) xs[i] = x[bb * 845 + i];
    for (int i = t; i < 1440; i += 256) ws[i] = w[i];
    if (t < 32) bs[t] = b[t];
    __syncthreads();
    for (int o = t; o < 1152; o += 256) {
        int oc = o / 36, r = o % 36, oy = r / 6, ox = r % 6;
        const float* wp = ws + oc * 45;
        const float* xp = xs + 2 * oy * 13 + 2 * ox;
        float a[5];
#pragma unroll
        for (int ic = 0; ic < 5; ic++) {
            a[ic] = 0.f;
#pragma unroll
            for (int ky = 0; ky < 3; ky++)
#pragma unroll
                for (int kx = 0; kx < 3; kx++)
                    a[ic] += xp[ic * 169 + ky * 13 + kx] * wp[ic * 9 + ky * 3 + kx];
        }
        float acc = bs[oc] + (((a[0] + a[1]) + (a[2] + a[3])) + a[4]);
        g_c1[bb * 1152 + o] = fmaxf(acc, 0.f);
    }
}

// ---------------- conv2: direct conv, 2x2 quadrant per thread ---------------
#define WST 292
__global__ void __launch_bounds__(256) conv2_kernel(const float* __restrict__ w,
                                                    const float* __restrict__ b) {
    __shared__ float ws[32 * WST];      // ~36.5KB
    __shared__ float imgs[2 * 1152];    // 9.2KB
    int bp = blockIdx.x >> 1;
    int oh = blockIdx.x & 1;
    int bb0 = bp * 2;
    int tid = threadIdx.x;

    const float4* wsrc = (const float4*)(w + oh * 9216);
    for (int i4 = tid; i4 < 2304; i4 += 256) {
        int o = i4 / 72, k4 = i4 % 72;
        *(float4*)(ws + o * WST + k4 * 4) = wsrc[i4];
    }
    {
        const float4* isrc = (const float4*)(g_c1 + bb0 * 1152);
        float4* idst = (float4*)imgs;
        for (int i = tid; i < 576; i += 256) idst[i] = isrc[i];
    }
    __syncthreads();

    int bi = tid >> 7;
    int oc = (tid >> 2) & 31;
    int qy = (tid >> 1) & 1, qx = tid & 1;
    const float* wp = ws + oc * WST;
    const float* ip = imgs + bi * 1152 + 2 * qy * 6 + 2 * qx;

    float a00 = 0.f, a01 = 0.f, a10 = 0.f, a11 = 0.f;
    for (int ic = 0; ic < 32; ic++) {
        float wr[9];
#pragma unroll
        for (int k = 0; k < 9; k++) wr[k] = wp[ic * 9 + k];
        float im[4][4];
#pragma unroll
        for (int r = 0; r < 4; r++) {
            float2 v0 = *(const float2*)(ip + ic * 36 + r * 6);
            float2 v1 = *(const float2*)(ip + ic * 36 + r * 6 + 2);
            im[r][0] = v0.x; im[r][1] = v0.y; im[r][2] = v1.x; im[r][3] = v1.y;
        }
#pragma unroll
        for (int ky = 0; ky < 3; ky++)
#pragma unroll
            for (int kx = 0; kx < 3; kx++) {
                float wv = wr[ky * 3 + kx];
                a00 += im[ky][kx] * wv;
                a01 += im[ky][kx + 1] * wv;
                a10 += im[ky + 1][kx] * wv;
                a11 += im[ky + 1][kx + 1] * wv;
            }
    }
    int ocg = oh * 32 + oc;
    float bias = b[ocg];
    float* op = g_c2 + (bb0 + bi) * 1024 + ocg * 16 + 2 * qy * 4 + 2 * qx;
    op[0] = fmaxf(a00 + bias, 0.f);
    op[1] = fmaxf(a01 + bias, 0.f);
    op[4] = fmaxf(a10 + bias, 0.f);
    op[5] = fmaxf(a11 + bias, 0.f);
}

// ---------------- FC: 32x32 tiles, 2x2 microtile, f32x2 FFMA2 --------------
__global__ void __launch_bounds__(256) fc_kernel(const float* __restrict__ W,  // [512,1024]
                                                 const float* __restrict__ b) {
    __shared__ float2 As2[16][33];
    __shared__ float  Bs[16][34];
    int tid = threadIdx.x;
    int tx = tid & 15, ty = tid >> 4;
    int row0 = blockIdx.y * 32, col0 = blockIdx.x * 32;
    int lrow = tid >> 3;
    int lkk  = (tid & 7) * 2;
    unsigned long long acc0 = 0ULL, acc1 = 0ULL;
    for (int k0 = 0; k0 < 1024; k0 += 16) {
        float2 av = *(const float2*)(g_c2 + (row0 + lrow) * 1024 + k0 + lkk);
        float2 bv = *(const float2*)(W + (col0 + lrow) * 1024 + k0 + lkk);
        As2[lkk][lrow]     = make_float2(av.x, av.x);
        As2[lkk + 1][lrow] = make_float2(av.y, av.y);
        Bs[lkk][lrow]      = bv.x;
        Bs[lkk + 1][lrow]  = bv.y;
        __syncthreads();
#pragma unroll
        for (int kk = 0; kk < 16; kk++) {
            unsigned long long a0 = *(const unsigned long long*)&As2[kk][ty * 2];
            unsigned long long a1 = *(const unsigned long long*)&As2[kk][ty * 2 + 1];
            unsigned long long bp = *(const unsigned long long*)&Bs[kk][tx * 2];
            acc0 = ffma2(a0, bp, acc0);
            acc1 = ffma2(a1, bp, acc1);
        }
        __syncthreads();
    }
    float o00, o01, o10, o11;
    unpackf2(acc0, o00, o01);
    unpackf2(acc1, o10, o11);
    int r0 = row0 + ty * 2, c0 = col0 + tx * 2;
    float b0 = b[c0], b1 = b[c0 + 1];
    g_hidden[r0 * 512 + c0]           = fmaxf(o00 + b0, 0.f);
    g_hidden[r0 * 512 + c0 + 1]       = fmaxf(o01 + b1, 0.f);
    g_hidden[(r0 + 1) * 512 + c0]     = fmaxf(o10 + b0, 0.f);
    g_hidden[(r0 + 1) * 512 + c0 + 1] = fmaxf(o11 + b1, 0.f);
}

// ---------------- logits + log_prob + entropy + action passthrough ----------
__global__ void logits_kernel(const float* __restrict__ Wmu,  // [21,512]
                              const float* __restrict__ bmu,
                              const int* __restrict__ action,
                              float* __restrict__ out_act,
                              float* __restrict__ lp_out,
                              float* __restrict__ ent_out) {
    __shared__ float lg[NACT];
    int bb = blockIdx.x;
    int lane = threadIdx.x;
    const float* h = g_hidden + bb * 512;
    float hreg[16];
#pragma unroll
    for (int i = 0; i < 16; i++) hreg[i] = h[lane + 32 * i];
    for (int o = 0; o < NACT; o++) {
        const float* wr = Wmu + o * 512;
        float acc = 0.f;
#pragma unroll
        for (int i = 0; i < 16; i++) acc += hreg[i] * wr[lane + 32 * i];
#pragma unroll
        for (int off = 16; off; off >>= 1) acc += __shfl_down_sync(0xffffffffu, acc, off);
        if (lane == 0) lg[o] = acc + bmu[o];
    }
    __syncwarp();
    if (lane == 0) {
        float m = -1e30f;
        for (int o = 0; o < NACT; o++) m = fmaxf(m, lg[o]);
        float s = 0.f;
        for (int o = 0; o < NACT; o++) s += expf(lg[o] - m);
        float lse = m + logf(s);
        float ent = 0.f;
        for (int o = 0; o < NACT; o++) {
            float lpo = lg[o] - lse;
            ent -= expf(lpo) * lpo;
        }
        lp_out[bb] = lg[action[bb]] - lse;
        ent_out[bb] = ent;
        out_act[bb] = (float)action[bb];
    }
}

// ---------------- actor_encoding row 0: GEMV (float4) -----------------------
__global__ void __launch_bounds__(256) ae0_kernel(const float* __restrict__ Wm,
                                                  const float* __restrict__ bm) {
    int wid = (blockIdx.x * blockDim.x + threadIdx.x) >> 5;
    int lane = threadIdx.x & 31;
    if (wid >= NA) return;
    const float4* wr = (const float4*)(Wm + wid * 512);
    const float4* hp = (const float4*)g_hidden;
    float acc = 0.f;
#pragma unroll
    for (int i = 0; i < 4; i++) {
        float4 w = wr[lane + 32 * i];
        float4 h = hp[lane + 32 * i];
        acc += w.x * h.x + w.y * h.y + w.z * h.z + w.w * h.w;
    }
#pragma unroll
    for (int off = 16; off; off >>= 1) acc += __shfl_down_sync(0xffffffffu, acc, off);
    if (lane == 0) g_ae0[wid] = acc + bm[wid];
}

// ---------------- graph prep ------------------------------------------------
__global__ void deg_kernel(const int* __restrict__ edge) {
    int idx = blockIdx.x * blockDim.x + threadIdx.x;
    if (idx >= NE) return;
    atomicAdd(&g_deg[edge[2 * idx + 1]], 1);
}

// dinv + b2l (idx<NA); transpose gcn2_w with LOG2E pre-scale; zero agg/agg2
__global__ void dinv_w2t_kernel(const float* __restrict__ w2,   // [16, 8192]
                                const float* __restrict__ b2) {
    int idx = blockIdx.x * blockDim.x + threadIdx.x;
    if (idx < NA) {
        g_dinv[idx] = rsqrtf((float)(g_deg[idx] + 1));  // +1 self-loop
        g_b2l[idx] = b2[idx] * LOG2E;
    }
    if (idx >= NA * 16) return;
    g_agg[idx] = 0.f;
    g_agg2[idx] = 0.f;
    int j = idx % NA, k = idx / NA;
    g_w2t[j * 16 + k] = w2[k * NA + j] * LOG2E;
}

// column sums of w2 + sum of b2, scaled by LOG2E (one block per row)
__global__ void __launch_bounds__(256) colsum_kernel(const float* __restrict__ w2,
                                                     const float* __restrict__ b2) {
    __shared__ float red[8];
    int row = blockIdx.x;
    int tid = threadIdx.x, lane = tid & 31, warp = tid >> 5;
    const float* src = (row < 16) ? (w2 + row * NA) : b2;
    const float4* p = (const float4*)src;
    float s = 0.f;
    for (int i = tid; i < NA / 4; i += 256) {
        float4 v = p[i];
        s += v.x + v.y + v.z + v.w;
    }
#pragma unroll
    for (int off = 16; off; off >>= 1) s += __shfl_down_sync(0xffffffffu, s, off);
    if (lane == 0) red[warp] = s;
    __syncthreads();
    if (tid == 0) {
        float t = 0.f;
#pragma unroll
        for (int w = 0; w < 8; w++) t += red[w];
        if (row < 16) g_colsum[row] = t * LOG2E;
        else g_sumb2l = t * LOG2E;
    }
}

// ------- scatter1 (fused feats@gcn1_w): agg[dst] += norm * (feat(src)@W1) ---
__global__ void scatter1_kernel(const float* __restrict__ x_msg,
                                const int* __restrict__ edge,
                                const float* __restrict__ w1) {  // [2,16]
    __shared__ float w1s[32];
    if (threadIdx.x < 32) w1s[threadIdx.x] = w1[threadIdx.x];
    __syncthreads();
    int e = blockIdx.x * blockDim.x + threadIdx.x;
    if (e >= NE + NA) return;
    int src, dst; float norm;
    if (e < NE) {
        int2 ed = ((const int2*)edge)[e];
        src = ed.x; dst = ed.y;
        norm = g_dinv[src] * g_dinv[dst];
    } else {
        src = dst = e - NE;
        float d = g_dinv[src];
        norm = d * d;
    }
    float f0 = x_msg[src] * norm;
    float f1 = g_ae0[src] * norm;
    float* out = g_agg + dst * 16;
    float h[16];
#pragma unroll
    for (int k = 0; k < 16; k++) h[k] = f0 * w1s[k] + f1 * w1s[16 + k];
    red4(out +  0, h[0],  h[1],  h[2],  h[3]);
    red4(out +  4, h[4],  h[5],  h[6],  h[7]);
    red4(out +  8, h[8],  h[9],  h[10], h[11]);
    red4(out + 12, h[12], h[13], h[14], h[15]);
}

// ------- scatter2 (fused relu+bias): agg2[dst] += norm * relu(agg[src]+b1) --
__global__ void scatter2_kernel(const int* __restrict__ edge,
                                const float* __restrict__ b1) {  // [16]
    __shared__ float b1s[16];
    if (threadIdx.x < 16) b1s[threadIdx.x] = b1[threadIdx.x];
    __syncthreads();
    int e = blockIdx.x * blockDim.x + threadIdx.x;
    if (e >= NE + NA) return;
    int src, dst; float norm;
    if (e < NE) {
        int2 ed = ((const int2*)edge)[e];
        src = ed.x; dst = ed.y;
        norm = g_dinv[src] * g_dinv[dst];
    } else {
        src = dst = e - NE;
        float d = g_dinv[src];
        norm = d * d;
    }
    const float4* in = (const float4*)(g_agg + src * 16);
    float* out = g_agg2 + dst * 16;
    float h[16];
#pragma unroll
    for (int q = 0; q < 4; q++) {
        float4 v = in[q];
        h[4 * q + 0] = fmaxf(v.x + b1s[4 * q + 0], 0.f) * norm;
        h[4 * q + 1] = fmaxf(v.y + b1s[4 * q + 1], 0.f) * norm;
        h[4 * q + 2] = fmaxf(v.z + b1s[4 * q + 2], 0.f) * norm;
        h[4 * q + 3] = fmaxf(v.w + b1s[4 * q + 3], 0.f) * norm;
    }
    red4(out +  0, h[0],  h[1],  h[2],  h[3]);
    red4(out +  4, h[4],  h[5],  h[6],  h[7]);
    red4(out +  8, h[8],  h[9],  h[10], h[11]);
    red4(out + 12, h[12], h[13], h[14], h[15]);
}

// ---------------- fused g2-row GEMM + log_softmax mean (register-A) ---------
// Each warp owns 8 rows (A in registers), lanes partition j (coalesced w2t).
// No shared memory in the inner loop; block = 8 warps x 8 rows = 64 rows.
__global__ void __launch_bounds__(256, 1)
rows_kernel(float* __restrict__ out) {
    int tid = threadIdx.x, lane = tid & 31, warp = tid >> 5;
    int row0 = blockIdx.x * 64 + warp * 8;

    unsigned long long au[8][8];
#pragma unroll
    for (int r = 0; r < 8; r++) {
        const ulonglong2* ap = (const ulonglong2*)(g_agg2 + (row0 + r) * 16);
#pragma unroll
        for (int q = 0; q < 4; q++) {
            ulonglong2 t = ap[q];
            au[r][2 * q] = t.x;
            au[r][2 * q + 1] = t.y;
        }
    }
    float se[8];
#pragma unroll
    for (int r = 0; r < 8; r++) se[r] = 0.f;

    for (int j = lane; j < NA; j += 32) {
        const ulonglong2* wp = (const ulonglong2*)(g_w2t + j * 16);
        ulonglong2 wa = wp[0], wb = wp[1], wc = wp[2], wd = wp[3];
        unsigned long long binit = packf2(g_b2l[j], 0.f);
#pragma unroll
        for (int r = 0; r < 8; r++) {
            unsigned long long acc = binit;
            acc = ffma2(au[r][0], wa.x, acc);
            acc = ffma2(au[r][1], wa.y, acc);
            acc = ffma2(au[r][2], wb.x, acc);
            acc = ffma2(au[r][3], wb.y, acc);
            acc = ffma2(au[r][4], wc.x, acc);
            acc = ffma2(au[r][5], wc.y, acc);
            acc = ffma2(au[r][6], wd.x, acc);
            acc = ffma2(au[r][7], wd.y, acc);
            float lo, hi;
            unpackf2(acc, lo, hi);
            se[r] += fexp2(lo + hi);
        }
    }

#pragma unroll
    for (int r = 0; r < 8; r++) {
#pragma unroll
        for (int off = 16; off; off >>= 1)
            se[r] += __shfl_down_sync(0xffffffffu, se[r], off);
    }
    if (lane == 0) {
        unsigned long long cs[8];
        const ulonglong2* cp = (const ulonglong2*)g_colsum;
#pragma unroll
        for (int q = 0; q < 4; q++) {
            ulonglong2 t = cp[q];
            cs[2 * q] = t.x;
            cs[2 * q + 1] = t.y;
        }
        float sb = g_sumb2l;
#pragma unroll
        for (int r = 0; r < 8; r++) {
            unsigned long long m = 0ULL;
#pragma unroll
            for (int k = 0; k < 8; k++) m = ffma2(au[r][k], cs[k], m);
            float lo, hi;
            unpackf2(m, lo, hi);
            float mean = sb + lo + hi;
            out[row0 + r] = LN2 * (mean * (1.f / (float)NA) - flog2(se[r]));
        }
    }
}

// ---------------- launch -----------------------------------------------------
extern "C" void kernel_launch(void* const* d_in, const int* in_sizes, int n_in,
                              void* d_out, int out_size) {
    const float* x       = (const float*)d_in[0];
    const float* x_msg   = (const float*)d_in[1];
    const int*   edge    = (const int*)d_in[2];
    const int*   action  = (const int*)d_in[3];
    const float* conv1_w = (const float*)d_in[4];
    const float* conv1_b = (const float*)d_in[5];
    const float* conv2_w = (const float*)d_in[6];
    const float* conv2_b = (const float*)d_in[7];
    const float* fc_w    = (const float*)d_in[8];
    const float* fc_b    = (const float*)d_in[9];
    const float* fcmu_w  = (const float*)d_in[10];
    const float* fcmu_b  = (const float*)d_in[11];
    const float* msg_w   = (const float*)d_in[12];
    const float* msg_b   = (const float*)d_in[13];
    const float* gcn1_w  = (const float*)d_in[14];
    const float* gcn1_b  = (const float*)d_in[15];
    const float* gcn2_w  = (const float*)d_in[16];
    const float* gcn2_b  = (const float*)d_in[17];

    float* out = (float*)d_out;
    float* out_msg = out + BATCH;
    float* out_lp  = out + BATCH + NA;
    float* out_ent = out + BATCH + NA + BATCH;

    void* p_deg;
    cudaGetSymbolAddress(&p_deg, g_deg);
    cudaMemsetAsync(p_deg, 0, NA * sizeof(int));

    deg_kernel<<<(NE + 255) / 256, 256>>>(edge);                         // k1
    dinv_w2t_kernel<<<(NA * 16 + 255) / 256, 256>>>(gcn2_w, gcn2_b);     // k2
    conv1_kernel<<<BATCH, 256>>>(x, conv1_w, conv1_b);                   // k3
    conv2_kernel<<<BATCH, 256>>>(conv2_w, conv2_b);                      // k4 <- profiled
    colsum_kernel<<<17, 256>>>(gcn2_w, gcn2_b);                          // k5
    fc_kernel<<<dim3(16, 8), 256>>>(fc_w, fc_b);
    logits_kernel<<<BATCH, 32>>>(fcmu_w, fcmu_b, action, out, out_lp, out_ent);
    ae0_kernel<<<NA * 32 / 256, 256>>>(msg_w, msg_b);

    scatter1_kernel<<<(NE + NA + 255) / 256, 256>>>(x_msg, edge, gcn1_w);
    scatter2_kernel<<<(NE + NA + 255) / 256, 256>>>(edge, gcn1_b);
    rows_kernel<<<NA / 64, 256>>>(out_msg);
}